// round 1
// baseline (speedup 1.0000x reference)
#include <cuda_runtime.h>
#include <cuda_bf16.h>

// Problem constants
#define BATCH 32
#define CIN   256
#define COUT  256
#define NEXP  8
#define CHID  64
#define HW    3136   // 56*56

// Device scratch (allocation-free per harness rules)
__device__ float g_pooled[BATCH * CIN];
__device__ float g_attn[BATCH * NEXP];
__device__ float g_wdyn[BATCH * COUT * CIN];   // 8 MB

// ---------------------------------------------------------------------------
// Kernel 1: global average pool over HW.  One block per (b, c) pair.
// ---------------------------------------------------------------------------
__global__ void pool_kernel(const float* __restrict__ x) {
    const int bc = blockIdx.x;                 // 0 .. BATCH*CIN-1
    const float* __restrict__ p = x + (size_t)bc * HW;
    const int tid = threadIdx.x;               // 256 threads

    float s = 0.0f;
    // HW = 3136 = 784 float4
    const float4* p4 = (const float4*)p;
    for (int i = tid; i < HW / 4; i += 256) {
        float4 v = p4[i];
        s += v.x + v.y + v.z + v.w;
    }
    // warp reduce
    for (int off = 16; off > 0; off >>= 1)
        s += __shfl_xor_sync(0xFFFFFFFFu, s, off);

    __shared__ float red[8];
    if ((tid & 31) == 0) red[tid >> 5] = s;
    __syncthreads();
    if (tid == 0) {
        float t = 0.0f;
        #pragma unroll
        for (int w = 0; w < 8; w++) t += red[w];
        g_pooled[bc] = t * (1.0f / (float)HW);
    }
}

// ---------------------------------------------------------------------------
// Kernel 2: MLP (256->64 relu ->8) + softmax -> attn[b, e]. One block per b.
// ---------------------------------------------------------------------------
__global__ void attn_kernel(const float* __restrict__ w1,
                            const float* __restrict__ b1,
                            const float* __restrict__ w2,
                            const float* __restrict__ b2) {
    const int b = blockIdx.x;
    const int t = threadIdx.x;                 // 64 threads

    __shared__ float sp[CIN];
    __shared__ float sh[CHID];
    __shared__ float sl[NEXP];

    for (int i = t; i < CIN; i += 64) sp[i] = g_pooled[b * CIN + i];
    __syncthreads();

    // h[t] = relu(w1[t,:] . pooled + b1[t])
    float acc = b1[t];
    const float* w1r = w1 + t * CIN;
    #pragma unroll 8
    for (int c = 0; c < CIN; c++) acc = fmaf(w1r[c], sp[c], acc);
    sh[t] = fmaxf(acc, 0.0f);
    __syncthreads();

    if (t < NEXP) {
        float l = b2[t];
        const float* w2r = w2 + t * CHID;
        #pragma unroll
        for (int j = 0; j < CHID; j++) l = fmaf(w2r[j], sh[j], l);
        sl[t] = l;
    }
    __syncthreads();

    if (t == 0) {
        float m = sl[0];
        #pragma unroll
        for (int e = 1; e < NEXP; e++) m = fmaxf(m, sl[e]);
        float sum = 0.0f;
        float ex[NEXP];
        #pragma unroll
        for (int e = 0; e < NEXP; e++) { ex[e] = __expf(sl[e] - m); sum += ex[e]; }
        float inv = 1.0f / sum;
        #pragma unroll
        for (int e = 0; e < NEXP; e++) g_attn[b * NEXP + e] = ex[e] * inv;
    }
}

// ---------------------------------------------------------------------------
// Kernel 3: w_dyn[b, co, :] = sum_e attn[b,e] * weights[e, co, :]
// One block per (b, co); 256 threads cover ci.
// ---------------------------------------------------------------------------
__global__ void wdyn_kernel(const float* __restrict__ weights) {
    const int idx = blockIdx.x;                // 0 .. BATCH*COUT-1
    const int b  = idx / COUT;
    const int co = idx % COUT;
    const int ci = threadIdx.x;

    float a[NEXP];
    #pragma unroll
    for (int e = 0; e < NEXP; e++) a[e] = g_attn[b * NEXP + e];

    float s = 0.0f;
    #pragma unroll
    for (int e = 0; e < NEXP; e++)
        s = fmaf(a[e], weights[((size_t)e * COUT + co) * CIN + ci], s);

    g_wdyn[((size_t)b * COUT + co) * CIN + ci] = s;
}

// ---------------------------------------------------------------------------
// Kernel 4: batched GEMM  out[b] = w_dyn[b] (256x256) @ x[b] (256x3136)
// BM=BN=64, BK=16, 256 threads, 4x4 microtile, float4 global loads.
// ---------------------------------------------------------------------------
#define BM 64
#define BN 64
#define BK 16

__global__ __launch_bounds__(256, 4)
void gemm_kernel(const float* __restrict__ x, float* __restrict__ out) {
    __shared__ float As[BK][BM];   // transposed A tile: As[k][m]
    __shared__ float Bs[BK][BN];

    const int b  = blockIdx.z;
    const int m0 = blockIdx.y * BM;
    const int n0 = blockIdx.x * BN;

    const float* __restrict__ A = g_wdyn + (size_t)b * COUT * CIN;  // [256,256]
    const float* __restrict__ B = x      + (size_t)b * CIN  * HW;   // [256,3136]
    float*       __restrict__ C = out    + (size_t)b * COUT * HW;

    const int tid = threadIdx.x;               // 256
    // A tile load mapping: 64 rows x 16 k  (float4 along k)
    const int arow  = tid >> 2;                // 0..63
    const int acol4 = (tid & 3) << 2;          // 0,4,8,12
    // B tile load mapping: 16 rows x 64 n  (float4 along n)
    const int brow  = tid >> 4;                // 0..15
    const int bcol4 = (tid & 15) << 2;         // 0..60
    // compute mapping
    const int tx = tid & 15;                   // n dir
    const int ty = tid >> 4;                   // m dir

    float acc[4][4];
    #pragma unroll
    for (int i = 0; i < 4; i++)
        #pragma unroll
        for (int j = 0; j < 4; j++) acc[i][j] = 0.0f;

    for (int k0 = 0; k0 < CIN; k0 += BK) {
        float4 av = *(const float4*)(A + (m0 + arow) * CIN + k0 + acol4);
        As[acol4 + 0][arow] = av.x;
        As[acol4 + 1][arow] = av.y;
        As[acol4 + 2][arow] = av.z;
        As[acol4 + 3][arow] = av.w;

        float4 bv = *(const float4*)(B + (size_t)(k0 + brow) * HW + n0 + bcol4);
        *(float4*)&Bs[brow][bcol4] = bv;

        __syncthreads();

        #pragma unroll
        for (int k = 0; k < BK; k++) {
            float4 a4 = *(const float4*)&As[k][ty << 2];
            float4 b4 = *(const float4*)&Bs[k][tx << 2];
            acc[0][0] = fmaf(a4.x, b4.x, acc[0][0]);
            acc[0][1] = fmaf(a4.x, b4.y, acc[0][1]);
            acc[0][2] = fmaf(a4.x, b4.z, acc[0][2]);
            acc[0][3] = fmaf(a4.x, b4.w, acc[0][3]);
            acc[1][0] = fmaf(a4.y, b4.x, acc[1][0]);
            acc[1][1] = fmaf(a4.y, b4.y, acc[1][1]);
            acc[1][2] = fmaf(a4.y, b4.z, acc[1][2]);
            acc[1][3] = fmaf(a4.y, b4.w, acc[1][3]);
            acc[2][0] = fmaf(a4.z, b4.x, acc[2][0]);
            acc[2][1] = fmaf(a4.z, b4.y, acc[2][1]);
            acc[2][2] = fmaf(a4.z, b4.z, acc[2][2]);
            acc[2][3] = fmaf(a4.z, b4.w, acc[2][3]);
            acc[3][0] = fmaf(a4.w, b4.x, acc[3][0]);
            acc[3][1] = fmaf(a4.w, b4.y, acc[3][1]);
            acc[3][2] = fmaf(a4.w, b4.z, acc[3][2]);
            acc[3][3] = fmaf(a4.w, b4.w, acc[3][3]);
        }
        __syncthreads();
    }

    #pragma unroll
    for (int i = 0; i < 4; i++) {
        float4 v = make_float4(acc[i][0], acc[i][1], acc[i][2], acc[i][3]);
        *(float4*)(C + (size_t)(m0 + (ty << 2) + i) * HW + n0 + (tx << 2)) = v;
    }
}

// ---------------------------------------------------------------------------
// Launch
// ---------------------------------------------------------------------------
extern "C" void kernel_launch(void* const* d_in, const int* in_sizes, int n_in,
                              void* d_out, int out_size) {
    const float* x       = (const float*)d_in[0];  // [32,256,56,56]
    const float* weights = (const float*)d_in[1];  // [8,256,256]
    const float* w1      = (const float*)d_in[2];  // [64,256]
    const float* b1      = (const float*)d_in[3];  // [64]
    const float* w2      = (const float*)d_in[4];  // [8,64]
    const float* b2      = (const float*)d_in[5];  // [8]
    float* out = (float*)d_out;                    // [32,256,56,56]

    pool_kernel<<<BATCH * CIN, 256>>>(x);
    attn_kernel<<<BATCH, 64>>>(w1, b1, w2, b2);
    wdyn_kernel<<<BATCH * COUT, 256>>>(weights);

    dim3 grid(HW / BN, COUT / BM, BATCH);          // 49 x 4 x 32
    gemm_kernel<<<grid, 256>>>(x, out);
}

// round 3
// speedup vs baseline: 1.5857x; 1.5857x over previous
#include <cuda_runtime.h>
#include <cuda_bf16.h>
#include <mma.h>

using namespace nvcuda;

// Problem constants
#define BATCH 32
#define CIN   256
#define COUT  256
#define NEXP  8
#define CHID  64
#define HW    3136   // 56*56

// GEMM tiling
#define BM 128
#define BN 64
#define BK 32
#define BKP 40            // padded A row (floats)
#define BNP 72            // padded B row (floats)
#define NCHUNKS (CIN / BK)

// dynamic smem layout (floats)
#define SM_A0 0
#define SM_A1 (BM * BKP)                       // 5120
#define SM_B0 (2 * BM * BKP)                   // 10240
#define SM_B1 (2 * BM * BKP + BK * BNP)        // 12544
#define SM_FLOATS (2 * BM * BKP + 2 * BK * BNP)  // 14848 -> 59392 bytes

// Device scratch (allocation-free per harness rules)
__device__ float g_pooled[BATCH * CIN];
__device__ float g_attn[BATCH * NEXP];
__device__ float g_wdyn[BATCH * COUT * CIN];   // 8 MB

__device__ __forceinline__ float tf32r(float f) {
    unsigned r;
    asm("cvt.rna.tf32.f32 %0, %1;" : "=r"(r) : "f"(f));
    return __uint_as_float(r);
}

// ---------------------------------------------------------------------------
// Kernel 1: global average pool
// ---------------------------------------------------------------------------
__global__ void pool_kernel(const float* __restrict__ x) {
    const int bc = blockIdx.x;
    const float* __restrict__ p = x + (size_t)bc * HW;
    const int tid = threadIdx.x;

    float s = 0.0f;
    const float4* p4 = (const float4*)p;
    for (int i = tid; i < HW / 4; i += 256) {
        float4 v = p4[i];
        s += v.x + v.y + v.z + v.w;
    }
    for (int off = 16; off > 0; off >>= 1)
        s += __shfl_xor_sync(0xFFFFFFFFu, s, off);

    __shared__ float red[8];
    if ((tid & 31) == 0) red[tid >> 5] = s;
    __syncthreads();
    if (tid == 0) {
        float t = 0.0f;
        #pragma unroll
        for (int w = 0; w < 8; w++) t += red[w];
        g_pooled[bc] = t * (1.0f / (float)HW);
    }
}

// ---------------------------------------------------------------------------
// Kernel 2: MLP + softmax -> attn
// ---------------------------------------------------------------------------
__global__ void attn_kernel(const float* __restrict__ w1,
                            const float* __restrict__ b1,
                            const float* __restrict__ w2,
                            const float* __restrict__ b2) {
    const int b = blockIdx.x;
    const int t = threadIdx.x;

    __shared__ float sp[CIN];
    __shared__ float sh[CHID];
    __shared__ float sl[NEXP];

    for (int i = t; i < CIN; i += 64) sp[i] = g_pooled[b * CIN + i];
    __syncthreads();

    float acc = b1[t];
    const float* w1r = w1 + t * CIN;
    #pragma unroll 8
    for (int c = 0; c < CIN; c++) acc = fmaf(w1r[c], sp[c], acc);
    sh[t] = fmaxf(acc, 0.0f);
    __syncthreads();

    if (t < NEXP) {
        float l = b2[t];
        const float* w2r = w2 + t * CHID;
        #pragma unroll
        for (int j = 0; j < CHID; j++) l = fmaf(w2r[j], sh[j], l);
        sl[t] = l;
    }
    __syncthreads();

    if (t == 0) {
        float m = sl[0];
        #pragma unroll
        for (int e = 1; e < NEXP; e++) m = fmaxf(m, sl[e]);
        float sum = 0.0f;
        float ex[NEXP];
        #pragma unroll
        for (int e = 0; e < NEXP; e++) { ex[e] = __expf(sl[e] - m); sum += ex[e]; }
        float inv = 1.0f / sum;
        #pragma unroll
        for (int e = 0; e < NEXP; e++) g_attn[b * NEXP + e] = ex[e] * inv;
    }
}

// ---------------------------------------------------------------------------
// Kernel 3: w_dyn = attn . weights
// ---------------------------------------------------------------------------
__global__ void wdyn_kernel(const float* __restrict__ weights) {
    const int idx = blockIdx.x;
    const int b  = idx / COUT;
    const int co = idx % COUT;
    const int ci = threadIdx.x;

    float a[NEXP];
    #pragma unroll
    for (int e = 0; e < NEXP; e++) a[e] = g_attn[b * NEXP + e];

    float s = 0.0f;
    #pragma unroll
    for (int e = 0; e < NEXP; e++)
        s = fmaf(a[e], weights[((size_t)e * COUT + co) * CIN + ci], s);

    g_wdyn[((size_t)b * COUT + co) * CIN + ci] = s;
}

// ---------------------------------------------------------------------------
// Kernel 4: wmma tf32 batched GEMM
//   out[b] (256 x 3136) = w_dyn[b] (256 x 256) @ x[b] (256 x 3136)
//   Per CTA: 128 x 64, K pipelined in 8 chunks of 32, double-buffered smem.
//   8 warps in 4x2; warp tile 32x32 = 2x2 m16n16k8 tf32 fragments.
// ---------------------------------------------------------------------------
__global__ __launch_bounds__(256)
void gemm_wmma(const float* __restrict__ x, float* __restrict__ out) {
    extern __shared__ float sm[];

    const int tid = threadIdx.x;
    const int wid = tid >> 5;
    const int wm = wid >> 1;          // 0..3
    const int wn = wid & 1;           // 0..1

    const int n0 = blockIdx.x * BN;
    const int m0 = blockIdx.y * BM;
    const int b  = blockIdx.z;

    const float* __restrict__ Ag = g_wdyn + (size_t)(b * COUT + m0) * CIN;
    const float* __restrict__ Bg = x + (size_t)b * CIN * HW;

    // load index precompute
    const int am  = (tid >> 3);       // base A row for i=0 slice (idx>>3)
    const int ak4 = (tid & 7) * 4;    // A k offset within chunk
    const int bk  = (tid >> 4);       // base B k-row for i=0 slice
    const int bn4 = (tid & 15) * 4;   // B n offset within tile

    wmma::fragment<wmma::accumulator, 16, 16, 8, float> acc[2][2];
    #pragma unroll
    for (int i = 0; i < 2; i++)
        #pragma unroll
        for (int j = 0; j < 2; j++)
            wmma::fill_fragment(acc[i][j], 0.0f);

    float4 aReg[4];
    float4 bReg[2];

    // ---- prologue: load + store chunk 0 ----
    #pragma unroll
    for (int i = 0; i < 4; i++)
        aReg[i] = *(const float4*)(Ag + (size_t)(am + i * 32) * CIN + ak4);
    #pragma unroll
    for (int i = 0; i < 2; i++)
        bReg[i] = *(const float4*)(Bg + (size_t)(bk + i * 16) * HW + n0 + bn4);

    #pragma unroll
    for (int i = 0; i < 4; i++) {
        float4 v = make_float4(tf32r(aReg[i].x), tf32r(aReg[i].y),
                               tf32r(aReg[i].z), tf32r(aReg[i].w));
        *(float4*)(sm + SM_A0 + (am + i * 32) * BKP + ak4) = v;
    }
    #pragma unroll
    for (int i = 0; i < 2; i++) {
        float4 v = make_float4(tf32r(bReg[i].x), tf32r(bReg[i].y),
                               tf32r(bReg[i].z), tf32r(bReg[i].w));
        *(float4*)(sm + SM_B0 + (bk + i * 16) * BNP + bn4) = v;
    }
    __syncthreads();

    for (int c = 0; c < NCHUNKS; c++) {
        // prefetch next chunk into registers (overlaps with MMA below)
        if (c < NCHUNKS - 1) {
            const int k0 = (c + 1) * BK;
            #pragma unroll
            for (int i = 0; i < 4; i++)
                aReg[i] = *(const float4*)(Ag + (size_t)(am + i * 32) * CIN + k0 + ak4);
            #pragma unroll
            for (int i = 0; i < 2; i++)
                bReg[i] = *(const float4*)(Bg + (size_t)(k0 + bk + i * 16) * HW + n0 + bn4);
        }

        const float* As = sm + (c & 1 ? SM_A1 : SM_A0);
        const float* Bs = sm + (c & 1 ? SM_B1 : SM_B0);

        #pragma unroll
        for (int ks = 0; ks < 4; ks++) {
            wmma::fragment<wmma::matrix_a, 16, 16, 8, wmma::precision::tf32, wmma::row_major> af[2];
            wmma::fragment<wmma::matrix_b, 16, 16, 8, wmma::precision::tf32, wmma::row_major> bf[2];
            #pragma unroll
            for (int i = 0; i < 2; i++)
                wmma::load_matrix_sync(af[i], As + (wm * 32 + i * 16) * BKP + ks * 8, BKP);
            #pragma unroll
            for (int j = 0; j < 2; j++)
                wmma::load_matrix_sync(bf[j], Bs + (ks * 8) * BNP + wn * 32 + j * 16, BNP);
            #pragma unroll
            for (int i = 0; i < 2; i++)
                #pragma unroll
                for (int j = 0; j < 2; j++)
                    wmma::mma_sync(acc[i][j], af[i], bf[j], acc[i][j]);
        }
        __syncthreads();

        if (c < NCHUNKS - 1) {
            float* An = sm + (c & 1 ? SM_A0 : SM_A1);
            float* Bn = sm + (c & 1 ? SM_B0 : SM_B1);
            #pragma unroll
            for (int i = 0; i < 4; i++) {
                float4 v = make_float4(tf32r(aReg[i].x), tf32r(aReg[i].y),
                                       tf32r(aReg[i].z), tf32r(aReg[i].w));
                *(float4*)(An + (am + i * 32) * BKP + ak4) = v;
            }
            #pragma unroll
            for (int i = 0; i < 2; i++) {
                float4 v = make_float4(tf32r(bReg[i].x), tf32r(bReg[i].y),
                                       tf32r(bReg[i].z), tf32r(bReg[i].w));
                *(float4*)(Bn + (bk + i * 16) * BNP + bn4) = v;
            }
            __syncthreads();
        }
    }

    // ---- epilogue: store accumulators ----
    float* __restrict__ C = out + (size_t)b * COUT * HW
                          + (size_t)(m0 + wm * 32) * HW + n0 + wn * 32;
    #pragma unroll
    for (int i = 0; i < 2; i++)
        #pragma unroll
        for (int j = 0; j < 2; j++)
            wmma::store_matrix_sync(C + (size_t)(i * 16) * HW + j * 16,
                                    acc[i][j], HW, wmma::mem_row_major);
}

// ---------------------------------------------------------------------------
// Launch
// ---------------------------------------------------------------------------
extern "C" void kernel_launch(void* const* d_in, const int* in_sizes, int n_in,
                              void* d_out, int out_size) {
    const float* x       = (const float*)d_in[0];
    const float* weights = (const float*)d_in[1];
    const float* w1      = (const float*)d_in[2];
    const float* b1      = (const float*)d_in[3];
    const float* w2      = (const float*)d_in[4];
    const float* b2      = (const float*)d_in[5];
    float* out = (float*)d_out;

    pool_kernel<<<BATCH * CIN, 256>>>(x);
    attn_kernel<<<BATCH, 64>>>(w1, b1, w2, b2);
    wdyn_kernel<<<BATCH * COUT, 256>>>(weights);

    static bool attr_set = false;
    if (!attr_set) {
        cudaFuncSetAttribute(gemm_wmma, cudaFuncAttributeMaxDynamicSharedMemorySize,
                             SM_FLOATS * (int)sizeof(float));
        attr_set = true;
    }

    dim3 grid(HW / BN, COUT / BM, BATCH);   // 49 x 2 x 32
    gemm_wmma<<<grid, 256, SM_FLOATS * sizeof(float)>>>(x, out);
}